// round 1
// baseline (speedup 1.0000x reference)
#include <cuda_runtime.h>
#include <math.h>
#include <stdint.h>

// Problem constants
#define TT 4096   // B*S tokens
#define DD 1024
#define NN 256
#define FF 4096
#define LL 8
#define SS 2048
#define BB 2
#define VV 32000
#define NCH 64    // scan chunks
#define SC  32    // steps per chunk

// ------------------- scratch (static device memory; no allocs) -------------
__device__ float g_x[TT * DD];
__device__ float g_h[TT * DD];
__device__ float g_ssm[TT * DD];
__device__ float g_n2[TT * DD];
__device__ float g_mid[(size_t)TT * FF];
__device__ float g_dt[TT * NN];
__device__ float g_decay[TT * NN];
__device__ float g_Bm[TT * NN];
__device__ float g_Cm[TT * NN];
__device__ float g_hsC[TT * NN];
__device__ float g_cE[BB * NCH * NN];
__device__ float g_cP[BB * NCH * NN];
__device__ float g_cI[BB * NCH * NN];

// ------------------- helpers ----------------------------------------------
__device__ __forceinline__ float softplusf(float x) {
    // stable log1p(exp(x))
    return x > 0.f ? x + log1pf(expf(-x)) : log1pf(expf(x));
}
__device__ __forceinline__ float geluf(float x) {
    // jax.nn.gelu approximate=True (tanh)
    float x3 = x * x * x;
    return 0.5f * x * (1.f + tanhf(0.7978845608028654f * (x + 0.044715f * x3)));
}

// ------------------- embedding gather --------------------------------------
__global__ void embed_kernel(const int* __restrict__ ids,
                             const float* __restrict__ emb,
                             float* __restrict__ x) {
    int t = blockIdx.x;
    int id = ids[t];
    const float4* src = (const float4*)(emb + (size_t)id * DD);
    float4* dst = (float4*)(x + (size_t)t * DD);
    dst[threadIdx.x] = src[threadIdx.x];
}

// ------------------- layernorm (one block per token, 256 thr) --------------
__global__ __launch_bounds__(256) void ln_kernel(const float* __restrict__ x,
                                                 const float* __restrict__ s,
                                                 const float* __restrict__ b,
                                                 float* __restrict__ out) {
    int t = blockIdx.x;
    int tid = threadIdx.x;
    float4 v = ((const float4*)(x + (size_t)t * DD))[tid];
    float sum = v.x + v.y + v.z + v.w;
    float sq  = v.x * v.x + v.y * v.y + v.z * v.z + v.w * v.w;
    #pragma unroll
    for (int o = 16; o > 0; o >>= 1) {
        sum += __shfl_xor_sync(0xffffffffu, sum, o);
        sq  += __shfl_xor_sync(0xffffffffu, sq, o);
    }
    __shared__ float s1[8], s2[8];
    int w = tid >> 5, lane = tid & 31;
    if (lane == 0) { s1[w] = sum; s2[w] = sq; }
    __syncthreads();
    float tot = 0.f, totq = 0.f;
    #pragma unroll
    for (int i = 0; i < 8; i++) { tot += s1[i]; totq += s2[i]; }
    float mean = tot * (1.f / DD);
    float var  = totq * (1.f / DD) - mean * mean;
    float inv  = rsqrtf(var + 1e-5f);
    float4 sv = ((const float4*)s)[tid];
    float4 bv = ((const float4*)b)[tid];
    float4 o;
    o.x = (v.x - mean) * inv * sv.x + bv.x;
    o.y = (v.y - mean) * inv * sv.y + bv.y;
    o.z = (v.z - mean) * inv * sv.z + bv.z;
    o.w = (v.w - mean) * inv * sv.w + bv.w;
    ((float4*)(out + (size_t)t * DD))[tid] = o;
}

// ------------------- SGEMM 128x128x16, 8x8 microtile, fused epilogues ------
// C[M,N] = A[M,K] @ B  (NN: B is K x N row-major; TB: B is N x K row-major)
// modes:
//  0: C = acc
//  1: dt = softplus(acc + bias[n]); C = dt; C2 = exp(dt * (-exp(p1[n])))
//  2: C = acc + p1[m,n]*bias[n] + p2[m,n]          (y + h*D_skip + res)
//  3: C = gelu(acc + bias[n])
//  4: C = acc + bias[n] + p1[m,n]                  (ffn out + residual)
template <bool TB>
__global__ __launch_bounds__(256) void sgemm(
    int M, int N, int K,
    const float* __restrict__ A, const float* __restrict__ B,
    float* __restrict__ C, float* __restrict__ C2,
    const float* __restrict__ bias, const float* __restrict__ p1,
    const float* __restrict__ p2, int mode)
{
    __shared__ float As[16][132];
    __shared__ float Bs[16][132];

    int tid = threadIdx.x;
    int tx = tid & 15, ty = tid >> 4;
    int m0 = blockIdx.y * 128, n0 = blockIdx.x * 128;

    float acc[8][8];
    #pragma unroll
    for (int i = 0; i < 8; i++)
        #pragma unroll
        for (int j = 0; j < 8; j++) acc[i][j] = 0.f;

    int arow = tid >> 2;          // 0..63
    int acol = (tid & 3) * 4;     // 0,4,8,12

    for (int k0 = 0; k0 < K; k0 += 16) {
        // A tile: 128x16, transpose into As[k][m]
        #pragma unroll
        for (int hh = 0; hh < 2; hh++) {
            int r = arow + hh * 64;
            float4 v = *(const float4*)&A[(size_t)(m0 + r) * K + k0 + acol];
            As[acol + 0][r] = v.x; As[acol + 1][r] = v.y;
            As[acol + 2][r] = v.z; As[acol + 3][r] = v.w;
        }
        if (TB) {
            // B is N x K row-major: tile 128(n) x 16(k), transpose into Bs[k][n]
            #pragma unroll
            for (int hh = 0; hh < 2; hh++) {
                int r = arow + hh * 64;
                float4 v = *(const float4*)&B[(size_t)(n0 + r) * K + k0 + acol];
                Bs[acol + 0][r] = v.x; Bs[acol + 1][r] = v.y;
                Bs[acol + 2][r] = v.z; Bs[acol + 3][r] = v.w;
            }
        } else {
            int brow = tid >> 5;          // 0..7
            int bcol = (tid & 31) * 4;    // 0..124
            #pragma unroll
            for (int hh = 0; hh < 2; hh++) {
                int r = brow + hh * 8;
                float4 v = *(const float4*)&B[(size_t)(k0 + r) * N + n0 + bcol];
                *(float4*)&Bs[r][bcol] = v;
            }
        }
        __syncthreads();

        #pragma unroll
        for (int kk = 0; kk < 16; kk++) {
            float ar[8], br[8];
            *(float4*)(ar)     = *(const float4*)&As[kk][ty * 8];
            *(float4*)(ar + 4) = *(const float4*)&As[kk][ty * 8 + 4];
            *(float4*)(br)     = *(const float4*)&Bs[kk][tx * 8];
            *(float4*)(br + 4) = *(const float4*)&Bs[kk][tx * 8 + 4];
            #pragma unroll
            for (int i = 0; i < 8; i++)
                #pragma unroll
                for (int j = 0; j < 8; j++)
                    acc[i][j] = fmaf(ar[i], br[j], acc[i][j]);
        }
        __syncthreads();
    }

    // epilogue
    int nbase = n0 + tx * 8;
    #pragma unroll
    for (int i = 0; i < 8; i++) {
        int m = m0 + ty * 8 + i;
        size_t rowoff = (size_t)m * N + nbase;
        float v[8], v2[8];
        #pragma unroll
        for (int j = 0; j < 8; j++) {
            int n = nbase + j;
            float a = acc[i][j];
            if (mode == 0) {
                v[j] = a;
            } else if (mode == 1) {
                float dtv = softplusf(a + bias[n]);
                v[j] = dtv;
                v2[j] = expf(dtv * (-expf(p1[n])));
            } else if (mode == 2) {
                v[j] = a + p1[rowoff + j] * bias[n] + p2[rowoff + j];
            } else if (mode == 3) {
                v[j] = geluf(a + bias[n]);
            } else { // 4
                v[j] = a + bias[n] + p1[rowoff + j];
            }
        }
        float* cp = C + rowoff;
        *(float4*)(cp)     = make_float4(v[0], v[1], v[2], v[3]);
        *(float4*)(cp + 4) = make_float4(v[4], v[5], v[6], v[7]);
        if (mode == 1) {
            float* cp2 = C2 + rowoff;
            *(float4*)(cp2)     = make_float4(v2[0], v2[1], v2[2], v2[3]);
            *(float4*)(cp2 + 4) = make_float4(v2[4], v2[5], v2[6], v2[7]);
        }
    }
}

// ------------------- chunked linear scan (3 passes) -------------------------
// h_t = decay_t * h_{t-1} + dt_t * Bm_t ;  output hsC_t = h_t * Cm_t
__global__ void scan_pass1(const float* __restrict__ decay,
                           const float* __restrict__ dt,
                           const float* __restrict__ Bm) {
    int n = threadIdx.x;
    int bc = blockIdx.x;                 // b*NCH + c
    int b = bc >> 6, c = bc & 63;
    int base = (b * SS + c * SC) * NN + n;
    float h = 0.f, p = 1.f;
    #pragma unroll 4
    for (int s = 0; s < SC; s++) {
        int idx = base + s * NN;
        float d = decay[idx];
        float bi = dt[idx] * Bm[idx];
        h = d * h + bi;
        p *= d;
    }
    g_cE[bc * NN + n] = h;
    g_cP[bc * NN + n] = p;
}

__global__ void scan_pass2() {
    int n = threadIdx.x;
    int b = blockIdx.x;
    float h = 0.f;
    #pragma unroll 8
    for (int c = 0; c < NCH; c++) {
        int idx = (b * NCH + c) * NN + n;
        g_cI[idx] = h;
        h = g_cP[idx] * h + g_cE[idx];
    }
}

__global__ void scan_pass3(const float* __restrict__ decay,
                           const float* __restrict__ dt,
                           const float* __restrict__ Bm,
                           const float* __restrict__ Cm,
                           float* __restrict__ hsC) {
    int n = threadIdx.x;
    int bc = blockIdx.x;
    int b = bc >> 6, c = bc & 63;
    int base = (b * SS + c * SC) * NN + n;
    float h = g_cI[bc * NN + n];
    #pragma unroll 4
    for (int s = 0; s < SC; s++) {
        int idx = base + s * NN;
        float d = decay[idx];
        float bi = dt[idx] * Bm[idx];
        h = d * h + bi;
        hsC[idx] = h * Cm[idx];
    }
}

// ------------------- launch -------------------------------------------------
extern "C" void kernel_launch(void* const* d_in, const int* in_sizes, int n_in,
                              void* d_out, int out_size) {
    const int*   ids    = (const int*)d_in[0];
    const float* emb    = (const float*)d_in[1];
    const float* A_log  = (const float*)d_in[2];
    const float* W_dt   = (const float*)d_in[3];
    const float* b_dt   = (const float*)d_in[4];
    const float* W_B    = (const float*)d_in[5];
    const float* W_C    = (const float*)d_in[6];
    const float* W_out  = (const float*)d_in[7];
    const float* D_skip = (const float*)d_in[8];
    const float* ln1_s  = (const float*)d_in[9];
    const float* ln1_b  = (const float*)d_in[10];
    const float* ln2_s  = (const float*)d_in[11];
    const float* ln2_b  = (const float*)d_in[12];
    const float* W1     = (const float*)d_in[13];
    const float* b1     = (const float*)d_in[14];
    const float* W2     = (const float*)d_in[15];
    const float* b2     = (const float*)d_in[16];
    const float* lnf_s  = (const float*)d_in[17];
    const float* lnf_b  = (const float*)d_in[18];
    float* out = (float*)d_out;

    float *x, *h, *ssm, *n2, *mid, *dt, *decay, *Bm, *Cm, *hsC;
    cudaGetSymbolAddress((void**)&x,    g_x);
    cudaGetSymbolAddress((void**)&h,    g_h);
    cudaGetSymbolAddress((void**)&ssm,  g_ssm);
    cudaGetSymbolAddress((void**)&n2,   g_n2);
    cudaGetSymbolAddress((void**)&mid,  g_mid);
    cudaGetSymbolAddress((void**)&dt,   g_dt);
    cudaGetSymbolAddress((void**)&decay,g_decay);
    cudaGetSymbolAddress((void**)&Bm,   g_Bm);
    cudaGetSymbolAddress((void**)&Cm,   g_Cm);
    cudaGetSymbolAddress((void**)&hsC,  g_hsC);

    embed_kernel<<<TT, 256>>>(ids, emb, x);

    for (int l = 0; l < LL; l++) {
        ln_kernel<<<TT, 256>>>(x, ln1_s + l * DD, ln1_b + l * DD, h);

        dim3 gN(NN / 128, TT / 128);   // (2, 32)
        sgemm<false><<<gN, 256>>>(TT, NN, DD, h, W_dt + (size_t)l * DD * NN,
                                  dt, decay, b_dt + l * NN, A_log + l * NN,
                                  nullptr, 1);
        sgemm<false><<<gN, 256>>>(TT, NN, DD, h, W_B + (size_t)l * DD * NN,
                                  Bm, nullptr, nullptr, nullptr, nullptr, 0);
        sgemm<false><<<gN, 256>>>(TT, NN, DD, h, W_C + (size_t)l * DD * NN,
                                  Cm, nullptr, nullptr, nullptr, nullptr, 0);

        scan_pass1<<<BB * NCH, 256>>>(decay, dt, Bm);
        scan_pass2<<<BB, 256>>>();
        scan_pass3<<<BB * NCH, 256>>>(decay, dt, Bm, Cm, hsC);

        dim3 gD(DD / 128, TT / 128);   // (8, 32)
        sgemm<false><<<gD, 256>>>(TT, DD, NN, hsC, W_out + (size_t)l * NN * DD,
                                  ssm, nullptr, D_skip + l * DD, h, x, 2);

        ln_kernel<<<TT, 256>>>(ssm, ln2_s + l * DD, ln2_b + l * DD, n2);

        dim3 gF(FF / 128, TT / 128);   // (32, 32)
        sgemm<false><<<gF, 256>>>(TT, FF, DD, n2, W1 + (size_t)l * DD * FF,
                                  mid, nullptr, b1 + l * FF, nullptr, nullptr, 3);
        sgemm<false><<<gD, 256>>>(TT, DD, FF, mid, W2 + (size_t)l * FF * DD,
                                  x, nullptr, b2 + l * DD, ssm, nullptr, 4);
    }

    ln_kernel<<<TT, 256>>>(x, lnf_s, lnf_b, h);
    dim3 gV(VV / 128, TT / 128);       // (250, 32)
    sgemm<true><<<gV, 256>>>(TT, VV, DD, h, emb, out,
                             nullptr, nullptr, nullptr, nullptr, 0);
}

// round 3
// speedup vs baseline: 2.4158x; 2.4158x over previous
#include <cuda_runtime.h>
#include <math.h>
#include <stdint.h>

// Problem constants
#define TT 4096   // B*S tokens
#define DD 1024
#define NNq 256
#define FFq 4096
#define LLq 8
#define SSq 2048
#define BBq 2
#define VVq 32000
#define NCHq 64
#define SCq  32

// ------------------- scratch ------------------------------------------------
__device__ float g_x[TT * DD];
__device__ float g_h[TT * DD];
__device__ float g_ssm[TT * DD];
__device__ float g_n2[TT * DD];
__device__ float g_mid[(size_t)TT * FFq];
__device__ float g_dt[TT * NNq];
__device__ float g_decay[TT * NNq];
__device__ float g_Bm[TT * NNq];
__device__ float g_Cm[TT * NNq];
__device__ float g_hsC[TT * NNq];
__device__ float g_cE[BBq * NCHq * NNq];
__device__ float g_cP[BBq * NCHq * NNq];
__device__ float g_cI[BBq * NCHq * NNq];

// ------------------- helpers ------------------------------------------------
__device__ __forceinline__ float softplusf(float x) {
    return x > 0.f ? x + log1pf(expf(-x)) : log1pf(expf(x));
}
__device__ __forceinline__ float geluf(float x) {
    float x3 = x * x * x;
    return 0.5f * x * (1.f + tanhf(0.7978845608028654f * (x + 0.044715f * x3)));
}
__device__ __forceinline__ uint32_t s2u(const void* p) {
    uint32_t a;
    asm("{ .reg .u64 t; cvta.to.shared.u64 t, %1; cvt.u32.u64 %0, t; }" : "=r"(a) : "l"(p));
    return a;
}
#define CPASYNC16(dst, src) \
    asm volatile("cp.async.cg.shared.global [%0], [%1], 16;" :: "r"(dst), "l"(src))
#define CPCOMMIT() asm volatile("cp.async.commit_group;" ::: "memory")

// ------------------- embedding gather ---------------------------------------
__global__ void embed_kernel(const int* __restrict__ ids,
                             const float* __restrict__ emb,
                             float* __restrict__ x) {
    int t = blockIdx.x;
    int id = ids[t];
    const float4* src = (const float4*)(emb + (size_t)id * DD);
    float4* dst = (float4*)(x + (size_t)t * DD);
    dst[threadIdx.x] = src[threadIdx.x];
}

// ------------------- layernorm ----------------------------------------------
__global__ __launch_bounds__(256) void ln_kernel(const float* __restrict__ x,
                                                 const float* __restrict__ s,
                                                 const float* __restrict__ b,
                                                 float* __restrict__ out) {
    int t = blockIdx.x;
    int tid = threadIdx.x;
    float4 v = ((const float4*)(x + (size_t)t * DD))[tid];
    float sum = v.x + v.y + v.z + v.w;
    float sq  = v.x * v.x + v.y * v.y + v.z * v.z + v.w * v.w;
    #pragma unroll
    for (int o = 16; o > 0; o >>= 1) {
        sum += __shfl_xor_sync(0xffffffffu, sum, o);
        sq  += __shfl_xor_sync(0xffffffffu, sq, o);
    }
    __shared__ float s1[8], s2[8];
    int w = tid >> 5, lane = tid & 31;
    if (lane == 0) { s1[w] = sum; s2[w] = sq; }
    __syncthreads();
    float tot = 0.f, totq = 0.f;
    #pragma unroll
    for (int i = 0; i < 8; i++) { tot += s1[i]; totq += s2[i]; }
    float mean = tot * (1.f / DD);
    float var  = totq * (1.f / DD) - mean * mean;
    float inv  = rsqrtf(var + 1e-5f);
    float4 sv = ((const float4*)s)[tid];
    float4 bv = ((const float4*)b)[tid];
    float4 o;
    o.x = (v.x - mean) * inv * sv.x + bv.x;
    o.y = (v.y - mean) * inv * sv.y + bv.y;
    o.z = (v.z - mean) * inv * sv.z + bv.z;
    o.w = (v.w - mean) * inv * sv.w + bv.w;
    ((float4*)(out + (size_t)t * DD))[tid] = o;
}

// ------------------- tf32 mma.sync GEMM --------------------------------------
// C[M,N] = A[M,K] @ B. Block tile 128x128, K-chunk 32, cp.async double buffer.
// TRANSB=true : B stored [K, Nglob] row-major (weights) -> smem Bs[k][n], str 136
// TRANSB=false: B stored [N, K]   row-major (emb)      -> smem Bs[n][k], str 36
// PROJ3: blockIdx.z in {0,1,2} selects (W_dt -> mode1, W_B, W_C).
// modes: 0: C=acc
//        1: dt=softplus(acc+bias[n]); C=dt; Caux=exp(dt*(-exp(p1[n])))
//        2: C=acc + p1[off]*bias[n] + p2[off]
//        3: C=gelu(acc+bias[n])
//        4: C=acc + bias[n] + p1[off]
#define AW 4608   // A tile words: 128*36
#define BW 4608   // B tile words (max of 128*36=4608, 32*136=4352)
#define BUFW (AW + BW)

template <bool TRANSB, bool PROJ3>
__global__ __launch_bounds__(256) void gemm_tc(
    int K, int ldc, int ldb,
    const float* __restrict__ A,
    const float* __restrict__ B0, const float* __restrict__ B1,
    const float* __restrict__ B2,
    float* __restrict__ O0, float* __restrict__ O1, float* __restrict__ O2,
    float* __restrict__ Caux,
    const float* __restrict__ bias, const float* __restrict__ p1,
    const float* __restrict__ p2, int mode)
{
    extern __shared__ __align__(16) float smem[];  // 2 * BUFW floats
    uint32_t sb = s2u(smem);

    int tid = threadIdx.x, wid = tid >> 5, lane = tid & 31;
    int g = lane >> 2, tq = lane & 3;
    int wm = wid >> 2, wn = wid & 3;          // 2 x 4 warp grid

    int m0 = blockIdx.x * 128;
    int n0 = blockIdx.y * 128;

    const float* Bsel;
    float* Csel;
    int mode_;
    if (PROJ3) {
        int sel = blockIdx.z;
        Bsel = sel == 0 ? B0 : (sel == 1 ? B1 : B2);
        Csel = sel == 0 ? O0 : (sel == 1 ? O1 : O2);
        mode_ = sel == 0 ? 1 : 0;
    } else {
        Bsel = B0; Csel = O0; mode_ = mode;
    }

    float c[4][4][4];
    #pragma unroll
    for (int i = 0; i < 4; i++)
        #pragma unroll
        for (int j = 0; j < 4; j++)
            #pragma unroll
            for (int r = 0; r < 4; r++) c[i][j][r] = 0.f;

    // staging index precompute
    int a_row = tid >> 3, a_kq = tid & 7;         // A: 4 iters of (row+=32)
    int NC = K >> 5;

    // ---- issue tile load for chunk `it` into buffer `buf` ----
    auto load_tile = [&](int it, int buf) {
        int kb = it * 32;
        uint32_t abase = sb + (uint32_t)(buf * BUFW) * 4u;
        uint32_t bbase = abase + AW * 4u;
        #pragma unroll
        for (int i = 0; i < 4; i++) {
            int row = a_row + i * 32;
            const float* src = A + (size_t)(m0 + row) * K + kb + a_kq * 4;
            CPASYNC16(abase + (uint32_t)(row * 36 + a_kq * 4) * 4u, src);
        }
        if (TRANSB) {
            int k = tid >> 3, n4 = (tid & 7) * 4;   // 4 iters of (n4 += 32)
            #pragma unroll
            for (int i = 0; i < 4; i++) {
                int n = n4 + i * 32;
                const float* src = Bsel + (size_t)(kb + k) * ldb + n0 + n;
                CPASYNC16(bbase + (uint32_t)(k * 136 + n) * 4u, src);
            }
        } else {
            int n = tid >> 3, kq = tid & 7;         // 4 iters of (n += 32)
            #pragma unroll
            for (int i = 0; i < 4; i++) {
                int nn = n + i * 32;
                const float* src = Bsel + (size_t)(n0 + nn) * ldb + kb + kq * 4;
                CPASYNC16(bbase + (uint32_t)(nn * 36 + kq * 4) * 4u, src);
            }
        }
        CPCOMMIT();
    };

    load_tile(0, 0);

    for (int it = 0; it < NC; ++it) {
        int buf = it & 1;
        if (it + 1 < NC) {
            load_tile(it + 1, buf ^ 1);
            asm volatile("cp.async.wait_group 1;" ::: "memory");
        } else {
            asm volatile("cp.async.wait_group 0;" ::: "memory");
        }
        __syncthreads();

        const uint32_t* As = (const uint32_t*)(smem + buf * BUFW);
        const uint32_t* Bs = (const uint32_t*)(smem + buf * BUFW + AW);

        #pragma unroll
        for (int ks = 0; ks < 4; ks++) {
            uint32_t af[4][4], bf[4][2];
            #pragma unroll
            for (int ma = 0; ma < 4; ma++) {
                int base = (wm * 64 + ma * 16 + g) * 36 + ks * 8 + tq;
                af[ma][0] = As[base];
                af[ma][1] = As[base + 8 * 36];
                af[ma][2] = As[base + 4];
                af[ma][3] = As[base + 8 * 36 + 4];
            }
            #pragma unroll
            for (int na = 0; na < 4; na++) {
                if (TRANSB) {
                    int base = (ks * 8 + tq) * 136 + wn * 32 + na * 8 + g;
                    bf[na][0] = Bs[base];
                    bf[na][1] = Bs[base + 4 * 136];
                } else {
                    int base = (wn * 32 + na * 8 + g) * 36 + ks * 8 + tq;
                    bf[na][0] = Bs[base];
                    bf[na][1] = Bs[base + 4];
                }
            }
            #pragma unroll
            for (int ma = 0; ma < 4; ma++)
                #pragma unroll
                for (int na = 0; na < 4; na++)
                    asm volatile(
                        "mma.sync.aligned.m16n8k8.row.col.f32.tf32.tf32.f32 "
                        "{%0,%1,%2,%3},{%4,%5,%6,%7},{%8,%9},{%0,%1,%2,%3};"
                        : "+f"(c[ma][na][0]), "+f"(c[ma][na][1]),
                          "+f"(c[ma][na][2]), "+f"(c[ma][na][3])
                        : "r"(af[ma][0]), "r"(af[ma][1]),
                          "r"(af[ma][2]), "r"(af[ma][3]),
                          "r"(bf[na][0]), "r"(bf[na][1]));
        }
        __syncthreads();
    }

    // ---- epilogue ----
    #pragma unroll
    for (int ma = 0; ma < 4; ma++) {
        int r0 = m0 + wm * 64 + ma * 16 + g;
        #pragma unroll
        for (int na = 0; na < 4; na++) {
            int col = n0 + wn * 32 + na * 8 + 2 * tq;
            #pragma unroll
            for (int half = 0; half < 2; half++) {
                int row = r0 + half * 8;
                size_t off = (size_t)row * ldc + col;
                float v0 = c[ma][na][half * 2];
                float v1 = c[ma][na][half * 2 + 1];
                if (mode_ == 0) {
                    *(float2*)(Csel + off) = make_float2(v0, v1);
                } else if (mode_ == 1) {
                    float d0 = softplusf(v0 + bias[col]);
                    float d1 = softplusf(v1 + bias[col + 1]);
                    *(float2*)(Csel + off) = make_float2(d0, d1);
                    float e0 = expf(d0 * (-expf(p1[col])));
                    float e1 = expf(d1 * (-expf(p1[col + 1])));
                    *(float2*)(Caux + off) = make_float2(e0, e1);
                } else if (mode_ == 2) {
                    float o0 = v0 + p1[off]     * bias[col]     + p2[off];
                    float o1 = v1 + p1[off + 1] * bias[col + 1] + p2[off + 1];
                    *(float2*)(Csel + off) = make_float2(o0, o1);
                } else if (mode_ == 3) {
                    *(float2*)(Csel + off) =
                        make_float2(geluf(v0 + bias[col]), geluf(v1 + bias[col + 1]));
                } else {
                    float o0 = v0 + bias[col]     + p1[off];
                    float o1 = v1 + bias[col + 1] + p1[off + 1];
                    *(float2*)(Csel + off) = make_float2(o0, o1);
                }
            }
        }
    }
}

// ------------------- chunked linear scan ------------------------------------
__global__ void scan_pass1(const float* __restrict__ decay,
                           const float* __restrict__ dt,
                           const float* __restrict__ Bm) {
    int n = threadIdx.x;
    int bc = blockIdx.x;
    int b = bc >> 6, cch = bc & 63;
    int base = (b * SSq + cch * SCq) * NNq + n;
    float h = 0.f, p = 1.f;
    #pragma unroll 4
    for (int s = 0; s < SCq; s++) {
        int idx = base + s * NNq;
        float d = decay[idx];
        float bi = dt[idx] * Bm[idx];
        h = d * h + bi;
        p *= d;
    }
    g_cE[bc * NNq + n] = h;
    g_cP[bc * NNq + n] = p;
}

__global__ void scan_pass2() {
    int n = threadIdx.x;
    int b = blockIdx.x;
    float h = 0.f;
    #pragma unroll 8
    for (int cch = 0; cch < NCHq; cch++) {
        int idx = (b * NCHq + cch) * NNq + n;
        g_cI[idx] = h;
        h = g_cP[idx] * h + g_cE[idx];
    }
}

__global__ void scan_pass3(const float* __restrict__ decay,
                           const float* __restrict__ dt,
                           const float* __restrict__ Bm,
                           const float* __restrict__ Cm,
                           float* __restrict__ hsC) {
    int n = threadIdx.x;
    int bc = blockIdx.x;
    int b = bc >> 6, cch = bc & 63;
    int base = (b * SSq + cch * SCq) * NNq + n;
    float h = g_cI[bc * NNq + n];
    #pragma unroll 4
    for (int s = 0; s < SCq; s++) {
        int idx = base + s * NNq;
        float d = decay[idx];
        float bi = dt[idx] * Bm[idx];
        h = d * h + bi;
        hsC[idx] = h * Cm[idx];
    }
}

// ------------------- launch --------------------------------------------------
extern "C" void kernel_launch(void* const* d_in, const int* in_sizes, int n_in,
                              void* d_out, int out_size) {
    const int*   ids    = (const int*)d_in[0];
    const float* emb    = (const float*)d_in[1];
    const float* A_log  = (const float*)d_in[2];
    const float* W_dt   = (const float*)d_in[3];
    const float* b_dt   = (const float*)d_in[4];
    const float* W_B    = (const float*)d_in[5];
    const float* W_C    = (const float*)d_in[6];
    const float* W_out  = (const float*)d_in[7];
    const float* D_skip = (const float*)d_in[8];
    const float* ln1_s  = (const float*)d_in[9];
    const float* ln1_b  = (const float*)d_in[10];
    const float* ln2_s  = (const float*)d_in[11];
    const float* ln2_b  = (const float*)d_in[12];
    const float* W1     = (const float*)d_in[13];
    const float* b1     = (const float*)d_in[14];
    const float* W2     = (const float*)d_in[15];
    const float* b2     = (const float*)d_in[16];
    const float* lnf_s  = (const float*)d_in[17];
    const float* lnf_b  = (const float*)d_in[18];
    float* out = (float*)d_out;

    float *x, *h, *ssm, *n2, *mid, *dt, *decay, *Bm, *Cm, *hsC;
    cudaGetSymbolAddress((void**)&x,     g_x);
    cudaGetSymbolAddress((void**)&h,     g_h);
    cudaGetSymbolAddress((void**)&ssm,   g_ssm);
    cudaGetSymbolAddress((void**)&n2,    g_n2);
    cudaGetSymbolAddress((void**)&mid,   g_mid);
    cudaGetSymbolAddress((void**)&dt,    g_dt);
    cudaGetSymbolAddress((void**)&decay, g_decay);
    cudaGetSymbolAddress((void**)&Bm,    g_Bm);
    cudaGetSymbolAddress((void**)&Cm,    g_Cm);
    cudaGetSymbolAddress((void**)&hsC,   g_hsC);

    const int SMEMB = 2 * BUFW * 4;  // 73,728 B
    cudaFuncSetAttribute(gemm_tc<true,  true >, cudaFuncAttributeMaxDynamicSharedMemorySize, SMEMB);
    cudaFuncSetAttribute(gemm_tc<true,  false>, cudaFuncAttributeMaxDynamicSharedMemorySize, SMEMB);
    cudaFuncSetAttribute(gemm_tc<false, false>, cudaFuncAttributeMaxDynamicSharedMemorySize, SMEMB);

    embed_kernel<<<TT, 256>>>(ids, emb, x);

    for (int l = 0; l < LLq; l++) {
        ln_kernel<<<TT, 256>>>(x, ln1_s + l * DD, ln1_b + l * DD, h);

        // fused dt / B / C projections (softplus & decay epilogue on z==0)
        gemm_tc<true, true><<<dim3(32, 2, 3), 256, SMEMB>>>(
            DD, NNq, NNq, h,
            W_dt + (size_t)l * DD * NNq, W_B + (size_t)l * DD * NNq,
            W_C + (size_t)l * DD * NNq,
            dt, Bm, Cm, decay,
            b_dt + l * NNq, A_log + l * NNq, nullptr, 0);

        scan_pass1<<<BBq * NCHq, 256>>>(decay, dt, Bm);
        scan_pass2<<<BBq, 256>>>();
        scan_pass3<<<BBq * NCHq, 256>>>(decay, dt, Bm, Cm, hsC);

        // y = (hs*C) @ W_out + h*D_skip + res
        gemm_tc<true, false><<<dim3(32, 8), 256, SMEMB>>>(
            NNq, DD, DD, hsC,
            W_out + (size_t)l * NNq * DD, nullptr, nullptr,
            ssm, nullptr, nullptr, nullptr,
            D_skip + l * DD, h, x, 2);

        ln_kernel<<<TT, 256>>>(ssm, ln2_s + l * DD, ln2_b + l * DD, n2);

        // FFN1: gelu(n2 @ W1 + b1)
        gemm_tc<true, false><<<dim3(32, 32), 256, SMEMB>>>(
            DD, FFq, FFq, n2,
            W1 + (size_t)l * DD * FFq, nullptr, nullptr,
            mid, nullptr, nullptr, nullptr,
            b1 + l * FFq, nullptr, nullptr, 3);

        // FFN2: mid @ W2 + b2 + ssm
        gemm_tc<true, false><<<dim3(32, 8), 256, SMEMB>>>(
            FFq, DD, DD, mid,
            W2 + (size_t)l * FFq * DD, nullptr, nullptr,
            x, nullptr, nullptr, nullptr,
            b2 + l * DD, ssm, nullptr, 4);
    }

    ln_kernel<<<TT, 256>>>(x, lnf_s, lnf_b, h);

    // logits: h @ emb^T  (emb is [V, D] = [N, K] row-major -> TRANSB=false)
    gemm_tc<false, false><<<dim3(32, 250), 256, SMEMB>>>(
        DD, VVq, DD, h,
        emb, nullptr, nullptr,
        out, nullptr, nullptr, nullptr,
        nullptr, nullptr, nullptr, 0);
}

// round 4
// speedup vs baseline: 3.4590x; 1.4318x over previous
#include <cuda_runtime.h>
#include <math.h>
#include <stdint.h>

// Problem constants
#define TT 4096   // B*S tokens
#define DD 1024
#define NNq 256
#define FFq 4096
#define LLq 8
#define SSq 2048
#define BBq 2
#define VVq 32000
#define NCHq 64
#define SCq  32

// ------------------- scratch ------------------------------------------------
__device__ float g_x[TT * DD];
__device__ float g_h[TT * DD];
__device__ float g_ssm[TT * DD];
__device__ float g_n2[TT * DD];
__device__ float g_mid[(size_t)TT * FFq];
__device__ float g_dt[TT * NNq];
__device__ float g_decay[TT * NNq];
__device__ float g_Bm[TT * NNq];
__device__ float g_Cm[TT * NNq];
__device__ float g_hsC[TT * NNq];
__device__ float g_cE[BBq * NCHq * NNq];
__device__ float g_cP[BBq * NCHq * NNq];
__device__ float g_cI[BBq * NCHq * NNq];

// ------------------- helpers ------------------------------------------------
__device__ __forceinline__ float softplusf(float x) {
    return x > 0.f ? x + log1pf(expf(-x)) : log1pf(expf(x));
}
__device__ __forceinline__ float geluf(float x) {
    float x3 = x * x * x;
    return 0.5f * x * (1.f + tanhf(0.7978845608028654f * (x + 0.044715f * x3)));
}
__device__ __forceinline__ uint32_t s2u(const void* p) {
    uint32_t a;
    asm("{ .reg .u64 t; cvta.to.shared.u64 t, %1; cvt.u32.u64 %0, t; }" : "=r"(a) : "l"(p));
    return a;
}
// round fp32 to nearest-even tf32 (result stays an fp32 bit-pattern)
__device__ __forceinline__ float rnd_tf32(float x) {
    uint32_t r;
    asm("cvt.rna.tf32.f32 %0, %1;" : "=r"(r) : "f"(x));
    return __uint_as_float(r);
}
__device__ __forceinline__ uint32_t rna_u(uint32_t x) {
    uint32_t r;
    asm("cvt.rna.tf32.f32 %0, %1;" : "=r"(r) : "f"(__uint_as_float(x)));
    return r;
}
#define CPASYNC16(dst, src) \
    asm volatile("cp.async.cg.shared.global [%0], [%1], 16;" :: "r"(dst), "l"(src))
#define CPCOMMIT() asm volatile("cp.async.commit_group;" ::: "memory")
#define LDSM4(r0, r1, r2, r3, addr) \
    asm volatile("ldmatrix.sync.aligned.m8n8.x4.shared.b16 {%0,%1,%2,%3}, [%4];" \
        : "=r"(r0), "=r"(r1), "=r"(r2), "=r"(r3) : "r"(addr))

// ------------------- embedding gather ---------------------------------------
__global__ void embed_kernel(const int* __restrict__ ids,
                             const float* __restrict__ emb,
                             float* __restrict__ x) {
    int t = blockIdx.x;
    int id = ids[t];
    const float4* src = (const float4*)(emb + (size_t)id * DD);
    float4* dst = (float4*)(x + (size_t)t * DD);
    dst[threadIdx.x] = src[threadIdx.x];
}

// ------------------- layernorm (output rounded to tf32-RNE) ------------------
__global__ __launch_bounds__(256) void ln_kernel(const float* __restrict__ x,
                                                 const float* __restrict__ s,
                                                 const float* __restrict__ b,
                                                 float* __restrict__ out) {
    int t = blockIdx.x;
    int tid = threadIdx.x;
    float4 v = ((const float4*)(x + (size_t)t * DD))[tid];
    float sum = v.x + v.y + v.z + v.w;
    float sq  = v.x * v.x + v.y * v.y + v.z * v.z + v.w * v.w;
    #pragma unroll
    for (int o = 16; o > 0; o >>= 1) {
        sum += __shfl_xor_sync(0xffffffffu, sum, o);
        sq  += __shfl_xor_sync(0xffffffffu, sq, o);
    }
    __shared__ float s1[8], s2[8];
    int w = tid >> 5, lane = tid & 31;
    if (lane == 0) { s1[w] = sum; s2[w] = sq; }
    __syncthreads();
    float tot = 0.f, totq = 0.f;
    #pragma unroll
    for (int i = 0; i < 8; i++) { tot += s1[i]; totq += s2[i]; }
    float mean = tot * (1.f / DD);
    float var  = totq * (1.f / DD) - mean * mean;
    float inv  = rsqrtf(var + 1e-5f);
    float4 sv = ((const float4*)s)[tid];
    float4 bv = ((const float4*)b)[tid];
    float4 o;
    o.x = rnd_tf32((v.x - mean) * inv * sv.x + bv.x);
    o.y = rnd_tf32((v.y - mean) * inv * sv.y + bv.y);
    o.z = rnd_tf32((v.z - mean) * inv * sv.z + bv.z);
    o.w = rnd_tf32((v.w - mean) * inv * sv.w + bv.w);
    ((float4*)(out + (size_t)t * DD))[tid] = o;
}

// ------------------- tf32 mma.sync GEMM --------------------------------------
// C[M,N] = A[M,K] @ B. Block tile 128x128, K-chunk 32, cp.async 3-stage.
// TRANSB=true : B stored [K, Nglob] row-major (weights) -> smem Bs[k][n], str 136
// TRANSB=false: B stored [N, K]   row-major (emb)      -> smem Bs[n][k], str 36
// A fragments via ldmatrix.x4; B fragments ldmatrix (!TRANSB) or scalar LDS.
// All B fragments rounded to tf32-RNE in-register. A assumed pre-rounded.
// PROJ3: blockIdx.z in {0,1,2} selects (W_dt -> mode1, W_B, W_C).
// modes: 0: C=acc
//        1: dt=softplus(acc+bias[n]); C=dt; Caux=exp(dt*(-exp(p1[n])))
//        2: C=acc + p1[off]*bias[n] + p2[off]
//        3: C=rnd(gelu(acc+bias[n]))
//        4: C=acc + bias[n] + p1[off]
#define AW 4608   // A tile words: 128*36
#define BW 4608   // B tile words (max of 128*36=4608, 32*136=4352)
#define BUFW (AW + BW)
#define NSTAGE 3

template <bool TRANSB, bool PROJ3>
__global__ __launch_bounds__(256, 2) void gemm_tc(
    int K, int ldc, int ldb,
    const float* __restrict__ A,
    const float* __restrict__ B0, const float* __restrict__ B1,
    const float* __restrict__ B2,
    float* __restrict__ O0, float* __restrict__ O1, float* __restrict__ O2,
    float* __restrict__ Caux,
    const float* __restrict__ bias, const float* __restrict__ p1,
    const float* __restrict__ p2, int mode)
{
    extern __shared__ __align__(16) float smem[];  // NSTAGE * BUFW floats
    uint32_t sb = s2u(smem);

    int tid = threadIdx.x, wid = tid >> 5, lane = tid & 31;
    int g = lane >> 2, tq = lane & 3;
    int wm = wid >> 2, wn = wid & 3;          // 2 x 4 warp grid

    int m0 = blockIdx.x * 128;
    int n0 = blockIdx.y * 128;

    const float* Bsel;
    float* Csel;
    int mode_;
    if (PROJ3) {
        int sel = blockIdx.z;
        Bsel = sel == 0 ? B0 : (sel == 1 ? B1 : B2);
        Csel = sel == 0 ? O0 : (sel == 1 ? O1 : O2);
        mode_ = sel == 0 ? 1 : 0;
    } else {
        Bsel = B0; Csel = O0; mode_ = mode;
    }

    float c[4][4][4];
    #pragma unroll
    for (int i = 0; i < 4; i++)
        #pragma unroll
        for (int j = 0; j < 4; j++)
            #pragma unroll
            for (int r = 0; r < 4; r++) c[i][j][r] = 0.f;

    // ldmatrix per-thread fragment byte offsets (within a buffer)
    int rowsel = lane & 15;
    int khalf  = (lane >> 4) * 4;   // words
    uint32_t a_frag = (uint32_t)(((wm * 64 + rowsel) * 36 + khalf) * 4);
    uint32_t b_frag0 = 0, b_frag1 = 0;
    if (!TRANSB) {
        b_frag0 = (uint32_t)(((wn * 32 + rowsel) * 36 + khalf) * 4);
        b_frag1 = (uint32_t)(((wn * 32 + 16 + rowsel) * 36 + khalf) * 4);
    }

    int a_row = tid >> 3, a_kq = tid & 7;
    int NC = K >> 5;

    auto load_tile = [&](int it, int buf) {
        int kb = it * 32;
        uint32_t abase = sb + (uint32_t)(buf * BUFW) * 4u;
        uint32_t bbase = abase + AW * 4u;
        #pragma unroll
        for (int i = 0; i < 4; i++) {
            int row = a_row + i * 32;
            const float* src = A + (size_t)(m0 + row) * K + kb + a_kq * 4;
            CPASYNC16(abase + (uint32_t)(row * 36 + a_kq * 4) * 4u, src);
        }
        if (TRANSB) {
            int k = tid >> 3, n4 = (tid & 7) * 4;
            #pragma unroll
            for (int i = 0; i < 4; i++) {
                int n = n4 + i * 32;
                const float* src = Bsel + (size_t)(kb + k) * ldb + n0 + n;
                CPASYNC16(bbase + (uint32_t)(k * 136 + n) * 4u, src);
            }
        } else {
            int n = tid >> 3, kq = tid & 7;
            #pragma unroll
            for (int i = 0; i < 4; i++) {
                int nn = n + i * 32;
                const float* src = Bsel + (size_t)(n0 + nn) * ldb + kb + kq * 4;
                CPASYNC16(bbase + (uint32_t)(nn * 36 + kq * 4) * 4u, src);
            }
        }
        CPCOMMIT();
    };

    load_tile(0, 0);
    if (NC > 1) load_tile(1, 1);

    int buf = 0;
    for (int it = 0; it < NC; ++it) {
        if (it + 2 < NC) {
            int bn = buf + 2; if (bn >= NSTAGE) bn -= NSTAGE;
            load_tile(it + 2, bn);
            asm volatile("cp.async.wait_group 2;" ::: "memory");
        } else if (it + 1 < NC) {
            asm volatile("cp.async.wait_group 1;" ::: "memory");
        } else {
            asm volatile("cp.async.wait_group 0;" ::: "memory");
        }
        __syncthreads();

        uint32_t abase = sb + (uint32_t)(buf * BUFW) * 4u;
        uint32_t bbase = abase + AW * 4u;
        const uint32_t* Bs = (const uint32_t*)(smem + buf * BUFW + AW);

        #pragma unroll
        for (int ks = 0; ks < 4; ks++) {
            uint32_t af[4][4], bf[4][2];
            #pragma unroll
            for (int ma = 0; ma < 4; ma++)
                LDSM4(af[ma][0], af[ma][1], af[ma][2], af[ma][3],
                      abase + a_frag + (uint32_t)(ma * 2304 + ks * 32));
            if (TRANSB) {
                #pragma unroll
                for (int na = 0; na < 4; na++) {
                    int base = (ks * 8 + tq) * 136 + wn * 32 + na * 8 + g;
                    bf[na][0] = rna_u(Bs[base]);
                    bf[na][1] = rna_u(Bs[base + 4 * 136]);
                }
            } else {
                uint32_t t0, t1, t2, t3;
                LDSM4(t0, t1, t2, t3, bbase + b_frag0 + (uint32_t)(ks * 32));
                bf[0][0] = rna_u(t0); bf[1][0] = rna_u(t1);
                bf[0][1] = rna_u(t2); bf[1][1] = rna_u(t3);
                LDSM4(t0, t1, t2, t3, bbase + b_frag1 + (uint32_t)(ks * 32));
                bf[2][0] = rna_u(t0); bf[3][0] = rna_u(t1);
                bf[2][1] = rna_u(t2); bf[3][1] = rna_u(t3);
            }
            #pragma unroll
            for (int ma = 0; ma < 4; ma++)
                #pragma unroll
                for (int na = 0; na < 4; na++)
                    asm volatile(
                        "mma.sync.aligned.m16n8k8.row.col.f32.tf32.tf32.f32 "
                        "{%0,%1,%2,%3},{%4,%5,%6,%7},{%8,%9},{%0,%1,%2,%3};"
                        : "+f"(c[ma][na][0]), "+f"(c[ma][na][1]),
                          "+f"(c[ma][na][2]), "+f"(c[ma][na][3])
                        : "r"(af[ma][0]), "r"(af[ma][1]),
                          "r"(af[ma][2]), "r"(af[ma][3]),
                          "r"(bf[na][0]), "r"(bf[na][1]));
        }
        __syncthreads();
        buf++; if (buf >= NSTAGE) buf = 0;
    }

    // ---- epilogue ----
    #pragma unroll
    for (int ma = 0; ma < 4; ma++) {
        int r0 = m0 + wm * 64 + ma * 16 + g;
        #pragma unroll
        for (int na = 0; na < 4; na++) {
            int col = n0 + wn * 32 + na * 8 + 2 * tq;
            #pragma unroll
            for (int half = 0; half < 2; half++) {
                int row = r0 + half * 8;
                size_t off = (size_t)row * ldc + col;
                float v0 = c[ma][na][half * 2];
                float v1 = c[ma][na][half * 2 + 1];
                if (mode_ == 0) {
                    *(float2*)(Csel + off) = make_float2(v0, v1);
                } else if (mode_ == 1) {
                    float d0 = softplusf(v0 + bias[col]);
                    float d1 = softplusf(v1 + bias[col + 1]);
                    *(float2*)(Csel + off) = make_float2(d0, d1);
                    float e0 = expf(d0 * (-expf(p1[col])));
                    float e1 = expf(d1 * (-expf(p1[col + 1])));
                    *(float2*)(Caux + off) = make_float2(e0, e1);
                } else if (mode_ == 2) {
                    float o0 = v0 + p1[off]     * bias[col]     + p2[off];
                    float o1 = v1 + p1[off + 1] * bias[col + 1] + p2[off + 1];
                    *(float2*)(Csel + off) = make_float2(o0, o1);
                } else if (mode_ == 3) {
                    *(float2*)(Csel + off) =
                        make_float2(rnd_tf32(geluf(v0 + bias[col])),
                                    rnd_tf32(geluf(v1 + bias[col + 1])));
                } else {
                    float o0 = v0 + bias[col]     + p1[off];
                    float o1 = v1 + bias[col + 1] + p1[off + 1];
                    *(float2*)(Csel + off) = make_float2(o0, o1);
                }
            }
        }
    }
}

// ------------------- chunked linear scan ------------------------------------
__global__ void scan_pass1(const float* __restrict__ decay,
                           const float* __restrict__ dt,
                           const float* __restrict__ Bm) {
    int n = threadIdx.x;
    int bc = blockIdx.x;
    int b = bc >> 6, cch = bc & 63;
    int base = (b * SSq + cch * SCq) * NNq + n;
    float h = 0.f, p = 1.f;
    #pragma unroll 4
    for (int s = 0; s < SCq; s++) {
        int idx = base + s * NNq;
        float d = decay[idx];
        float bi = dt[idx] * Bm[idx];
        h = d * h + bi;
        p *= d;
    }
    g_cE[bc * NNq + n] = h;
    g_cP[bc * NNq + n] = p;
}

__global__ void scan_pass2() {
    int n = threadIdx.x;
    int b = blockIdx.x;
    float h = 0.f;
    #pragma unroll 8
    for (int cch = 0; cch < NCHq; cch++) {
        int idx = (b * NCHq + cch) * NNq + n;
        g_cI[idx] = h;
        h = g_cP[idx] * h + g_cE[idx];
    }
}

__global__ void scan_pass3(const float* __restrict__ decay,
                           const float* __restrict__ dt,
                           const float* __restrict__ Bm,
                           const float* __restrict__ Cm,
                           float* __restrict__ hsC) {
    int n = threadIdx.x;
    int bc = blockIdx.x;
    int b = bc >> 6, cch = bc & 63;
    int base = (b * SSq + cch * SCq) * NNq + n;
    float h = g_cI[bc * NNq + n];
    #pragma unroll 4
    for (int s = 0; s < SCq; s++) {
        int idx = base + s * NNq;
        float d = decay[idx];
        float bi = dt[idx] * Bm[idx];
        h = d * h + bi;
        hsC[idx] = rnd_tf32(h * Cm[idx]);
    }
}

// ------------------- launch --------------------------------------------------
extern "C" void kernel_launch(void* const* d_in, const int* in_sizes, int n_in,
                              void* d_out, int out_size) {
    const int*   ids    = (const int*)d_in[0];
    const float* emb    = (const float*)d_in[1];
    const float* A_log  = (const float*)d_in[2];
    const float* W_dt   = (const float*)d_in[3];
    const float* b_dt   = (const float*)d_in[4];
    const float* W_B    = (const float*)d_in[5];
    const float* W_C    = (const float*)d_in[6];
    const float* W_out  = (const float*)d_in[7];
    const float* D_skip = (const float*)d_in[8];
    const float* ln1_s  = (const float*)d_in[9];
    const float* ln1_b  = (const float*)d_in[10];
    const float* ln2_s  = (const float*)d_in[11];
    const float* ln2_b  = (const float*)d_in[12];
    const float* W1     = (const float*)d_in[13];
    const float* b1     = (const float*)d_in[14];
    const float* W2     = (const float*)d_in[15];
    const float* b2     = (const float*)d_in[16];
    const float* lnf_s  = (const float*)d_in[17];
    const float* lnf_b  = (const float*)d_in[18];
    float* out = (float*)d_out;

    float *x, *h, *ssm, *n2, *mid, *dt, *decay, *Bm, *Cm, *hsC;
    cudaGetSymbolAddress((void**)&x,     g_x);
    cudaGetSymbolAddress((void**)&h,     g_h);
    cudaGetSymbolAddress((void**)&ssm,   g_ssm);
    cudaGetSymbolAddress((void**)&n2,    g_n2);
    cudaGetSymbolAddress((void**)&mid,   g_mid);
    cudaGetSymbolAddress((void**)&dt,    g_dt);
    cudaGetSymbolAddress((void**)&decay, g_decay);
    cudaGetSymbolAddress((void**)&Bm,    g_Bm);
    cudaGetSymbolAddress((void**)&Cm,    g_Cm);
    cudaGetSymbolAddress((void**)&hsC,   g_hsC);

    const int SMEMB = NSTAGE * BUFW * 4;  // 110,592 B
    cudaFuncSetAttribute(gemm_tc<true,  true >, cudaFuncAttributeMaxDynamicSharedMemorySize, SMEMB);
    cudaFuncSetAttribute(gemm_tc<true,  false>, cudaFuncAttributeMaxDynamicSharedMemorySize, SMEMB);
    cudaFuncSetAttribute(gemm_tc<false, false>, cudaFuncAttributeMaxDynamicSharedMemorySize, SMEMB);

    embed_kernel<<<TT, 256>>>(ids, emb, x);

    for (int l = 0; l < LLq; l++) {
        ln_kernel<<<TT, 256>>>(x, ln1_s + l * DD, ln1_b + l * DD, h);

        // fused dt / B / C projections (softplus & decay epilogue on z==0)
        gemm_tc<true, true><<<dim3(32, 2, 3), 256, SMEMB>>>(
            DD, NNq, NNq, h,
            W_dt + (size_t)l * DD * NNq, W_B + (size_t)l * DD * NNq,
            W_C + (size_t)l * DD * NNq,
            dt, Bm, Cm, decay,
            b_dt + l * NNq, A_log + l * NNq, nullptr, 0);

        scan_pass1<<<BBq * NCHq, 256>>>(decay, dt, Bm);
        scan_pass2<<<BBq, 256>>>();
        scan_pass3<<<BBq * NCHq, 256>>>(decay, dt, Bm, Cm, hsC);

        // y = (hs*C) @ W_out + h*D_skip + res
        gemm_tc<true, false><<<dim3(32, 8), 256, SMEMB>>>(
            NNq, DD, DD, hsC,
            W_out + (size_t)l * NNq * DD, nullptr, nullptr,
            ssm, nullptr, nullptr, nullptr,
            D_skip + l * DD, h, x, 2);

        ln_kernel<<<TT, 256>>>(ssm, ln2_s + l * DD, ln2_b + l * DD, n2);

        // FFN1: gelu(n2 @ W1 + b1)
        gemm_tc<true, false><<<dim3(32, 32), 256, SMEMB>>>(
            DD, FFq, FFq, n2,
            W1 + (size_t)l * DD * FFq, nullptr, nullptr,
            mid, nullptr, nullptr, nullptr,
            b1 + l * FFq, nullptr, nullptr, 3);

        // FFN2: mid @ W2 + b2 + ssm
        gemm_tc<true, false><<<dim3(32, 8), 256, SMEMB>>>(
            FFq, DD, DD, mid,
            W2 + (size_t)l * FFq * DD, nullptr, nullptr,
            x, nullptr, nullptr, nullptr,
            b2 + l * DD, ssm, nullptr, 4);
    }

    ln_kernel<<<TT, 256>>>(x, lnf_s, lnf_b, h);

    // logits: h @ emb^T  (emb is [V, D] = [N, K] row-major -> TRANSB=false)
    gemm_tc<false, false><<<dim3(32, 250), 256, SMEMB>>>(
        DD, VVq, DD, h,
        emb, nullptr, nullptr,
        out, nullptr, nullptr, nullptr,
        nullptr, nullptr, nullptr, 0);
}